// round 1
// baseline (speedup 1.0000x reference)
#include <cuda_runtime.h>
#include <math.h>

// Problem constants
#define NROWS   131072          // 32*64*64 spatial positions
#define DDIM    64
#define KCODES  512
#define KTILE   256
#define QSIZE   8388608         // 32*64*64*64
#define ENCSIZE 67108864        // NROWS*KCODES
#define ENC_OFF (QSIZE + 1)
#define PERP_OFF (QSIZE + 1 + ENCSIZE)

// Scratch (static device globals — no allocation allowed)
__device__ int    g_idx[NROWS];
__device__ int    g_counts[KCODES];
__device__ double g_loss;
__device__ float  g_w2[KCODES];

__global__ void init_kernel() {
    int t = threadIdx.x;
    if (t < KCODES) g_counts[t] = 0;
    if (t == 0) g_loss = 0.0;
}

// w2[k] = sum_i round(w[k][i]^2), sequential non-fused adds (mimic jnp.sum(w*w,axis=1)).
__global__ void w2_kernel(const float* __restrict__ w) {
    int k = blockIdx.x * blockDim.x + threadIdx.x;
    if (k < KCODES) {
        float s = 0.0f;
        #pragma unroll 8
        for (int i = 0; i < DDIM; ++i) {
            float v = w[k * DDIM + i];
            s = __fadd_rn(s, __fmul_rn(v, v));
        }
        g_w2[k] = s;
    }
}

// Main kernel: one thread per row. Computes S, the 512 distances with
// reference-identical rounding, argmin (first-index tie-break), quantized
// output (straight-through rounding replicated), loss partial sums, histogram.
__global__ __launch_bounds__(256, 2)
void main_kernel(const float* __restrict__ x, const float* __restrict__ w,
                 float* __restrict__ out) {
    __shared__ __align__(16) float wt[DDIM][KTILE + 4];  // transposed tile, padded
    __shared__ float w2s[KCODES];
    __shared__ int   hist[KCODES];

    int tid = threadIdx.x;
    for (int i = tid; i < KCODES; i += 256) { hist[i] = 0; w2s[i] = g_w2[i]; }

    int row = blockIdx.x * 256 + tid;            // grid is exactly 512 blocks
    int b   = row >> 12;                         // row = b*4096 + h*64 + w
    int hw  = row & 4095;
    const float* xp = x + (size_t)b * 262144 + hw;  // x[b, c, h, w], stride 4096 over c

    float f[DDIM];
    #pragma unroll
    for (int c = 0; c < DDIM; ++c) f[c] = xp[c * 4096];

    // S = sum(f*f): sequential, NON-fused (jnp squares then reduces).
    float S = 0.0f;
    #pragma unroll
    for (int c = 0; c < DDIM; ++c) S = __fadd_rn(S, __fmul_rn(f[c], f[c]));

    float dmin = __int_as_float(0x7f800000);     // +inf
    int   kbest = 0;

    for (int kt = 0; kt < KCODES; kt += KTILE) {
        __syncthreads();
        // Cooperative transposed tile load: wt[i][kk] = w[kt+kk][i]
        for (int idx = tid; idx < KTILE * DDIM; idx += 256) {
            int i  = idx & 63;
            int kk = idx >> 6;
            wt[i][kk] = w[(size_t)(kt + kk) * DDIM + i];
        }
        __syncthreads();

        for (int kk = 0; kk < KTILE; kk += 8) {
            float a[8];
            #pragma unroll
            for (int j = 0; j < 8; ++j) a[j] = 0.0f;

            // 8 independent sequential-order fma chains (ILP 8 hides FMA latency;
            // each chain's i-order stays 0..63 to match the reference dot).
            #pragma unroll
            for (int i = 0; i < DDIM; ++i) {
                float4 wa = *(const float4*)&wt[i][kk];
                float4 wb = *(const float4*)&wt[i][kk + 4];
                a[0] = fmaf(f[i], wa.x, a[0]);
                a[1] = fmaf(f[i], wa.y, a[1]);
                a[2] = fmaf(f[i], wa.z, a[2]);
                a[3] = fmaf(f[i], wa.w, a[3]);
                a[4] = fmaf(f[i], wb.x, a[4]);
                a[5] = fmaf(f[i], wb.y, a[5]);
                a[6] = fmaf(f[i], wb.z, a[6]);
                a[7] = fmaf(f[i], wb.w, a[7]);
            }
            #pragma unroll
            for (int j = 0; j < 8; ++j) {
                int k = kt + kk + j;
                // ref: t1 = fl(S + w2[k]); d = fl(t1 - fl(2*fw)); 2*fw exact -> fused ok
                float t1 = __fadd_rn(S, w2s[k]);
                float d  = fmaf(-2.0f, a[j], t1);
                if (d < dmin) { dmin = d; kbest = k; }   // strict <: first index wins
            }
        }
    }

    g_idx[row] = kbest;
    atomicAdd(&hist[kbest], 1);

    // Quantized output (straight-through forward: fl(x + fl(q - x))) + loss partials
    const float* wr = w + (size_t)kbest * DDIM;
    float* qo = out + (size_t)b * 262144 + hw;
    float lsum = 0.0f;
    #pragma unroll
    for (int c = 0; c < DDIM; ++c) {
        float q  = wr[c];
        float dd = __fsub_rn(q, f[c]);
        qo[c * 4096] = __fadd_rn(f[c], dd);
        lsum = fmaf(dd, dd, lsum);
    }
    // warp-reduce loss, one double atomic per warp
    #pragma unroll
    for (int o = 16; o; o >>= 1) lsum += __shfl_down_sync(0xffffffffu, lsum, o);
    if ((tid & 31) == 0) atomicAdd(&g_loss, (double)lsum);

    __syncthreads();
    for (int i = tid; i < KCODES; i += 256)
        if (hist[i]) atomicAdd(&g_counts[i], hist[i]);
}

// One-hot encodings: 67.1M coalesced scalar stores (base offset is odd, so no
// vector alignment available).
__global__ void enc_kernel(float* __restrict__ enc) {
    unsigned int i = blockIdx.x * 256u + threadIdx.x;  // exactly ENCSIZE threads
    int n = i >> 9;
    int k = i & 511;
    enc[i] = (g_idx[n] == k) ? 1.0f : 0.0f;
}

__global__ void final_kernel(float* __restrict__ out) {
    __shared__ double red[KCODES];
    int t = threadIdx.x;
    float p = (float)g_counts[t] * (1.0f / 131072.0f);   // exact (power-of-2 divide)
    float term = __fmul_rn(p, logf(__fadd_rn(p, 1e-10f)));
    red[t] = (double)term;
    __syncthreads();
    for (int s = 256; s; s >>= 1) {
        if (t < s) red[t] += red[t + s];
        __syncthreads();
    }
    if (t == 0) {
        out[PERP_OFF] = expf(-(float)red[0]);
        float m = (float)(g_loss / (double)QSIZE);
        // loss = q_latent + 0.25*e_latent; both equal m in forward
        out[QSIZE] = __fadd_rn(m, __fmul_rn(0.25f, m));
    }
}

extern "C" void kernel_launch(void* const* d_in, const int* in_sizes, int n_in,
                              void* d_out, int out_size) {
    const float* x = (const float*)d_in[0];
    const float* w = (const float*)d_in[1];
    float* out = (float*)d_out;

    init_kernel<<<1, 512>>>();
    w2_kernel<<<1, 512>>>(w);
    main_kernel<<<NROWS / 256, 256>>>(x, w, out);
    enc_kernel<<<ENCSIZE / 256, 256>>>(out + ENC_OFF);
    final_kernel<<<1, KCODES>>>(out);
}

// round 2
// speedup vs baseline: 1.2955x; 1.2955x over previous
#include <cuda_runtime.h>
#include <math.h>

// Problem constants
#define NROWS   131072          // 32*64*64 spatial positions
#define DDIM    64
#define KCODES  512
#define KTILE   256
#define QSIZE   8388608         // 32*64*64*64
#define ENCSIZE 67108864        // NROWS*KCODES
#define ENC_OFF (QSIZE + 1)
#define PERP_OFF (QSIZE + 1 + ENCSIZE)

// Scratch (static device globals — no allocation allowed)
__device__ int    g_idx[NROWS];
__device__ int    g_counts[KCODES];
__device__ double g_loss;
__device__ float  g_w2[KCODES];

__global__ void init_kernel() {
    int t = threadIdx.x;
    if (t < KCODES) g_counts[t] = 0;
    if (t == 0) g_loss = 0.0;
}

// w2[k] = sum_i round(w[k][i]^2), sequential non-fused adds (mimic jnp.sum(w*w,axis=1)).
__global__ void w2_kernel(const float* __restrict__ w) {
    int k = blockIdx.x * blockDim.x + threadIdx.x;
    if (k < KCODES) {
        float s = 0.0f;
        #pragma unroll 8
        for (int i = 0; i < DDIM; ++i) {
            float v = w[k * DDIM + i];
            s = __fadd_rn(s, __fmul_rn(v, v));
        }
        g_w2[k] = s;
    }
}

// Packed dual-FMA: two independent fp32 fma.rn per instruction (bit-exact per lane).
__device__ __forceinline__ void ffma2(unsigned long long& acc,
                                      unsigned long long f2,
                                      unsigned long long w2) {
    asm("fma.rn.f32x2 %0, %1, %2, %0;" : "+l"(acc) : "l"(f2), "l"(w2));
}

// Main kernel: one thread per row. Distances with reference-identical rounding,
// argmin (first-index tie-break), quantized output, loss partials, histogram.
__global__ __launch_bounds__(256, 2)
void main_kernel(const float* __restrict__ x, const float* __restrict__ w,
                 float* __restrict__ out) {
    __shared__ __align__(16) float wt[DDIM][KTILE + 4];  // transposed tile; row stride 1040B (16B-mult)
    __shared__ float w2s[KCODES];
    __shared__ int   hist[KCODES];

    int tid = threadIdx.x;
    for (int i = tid; i < KCODES; i += 256) { hist[i] = 0; w2s[i] = g_w2[i]; }

    int row = blockIdx.x * 256 + tid;            // grid is exactly 512 blocks
    int b   = row >> 12;                         // row = b*4096 + hw
    int hw  = row & 4095;
    const float* xp = x + (size_t)b * 262144 + hw;  // x[b, c, h, w], stride 4096 over c

    float f[DDIM];
    #pragma unroll
    for (int c = 0; c < DDIM; ++c) f[c] = xp[c * 4096];

    // S = sum(f*f): sequential, NON-fused (jnp squares then reduces).
    float S = 0.0f;
    #pragma unroll
    for (int c = 0; c < DDIM; ++c) S = __fadd_rn(S, __fmul_rn(f[c], f[c]));

    float dmin = __int_as_float(0x7f800000);     // +inf
    int   kbest = 0;

    for (int kt = 0; kt < KCODES; kt += KTILE) {
        __syncthreads();
        // Cooperative transposed tile load: wt[i][kk] = w[kt+kk][i]
        for (int idx = tid; idx < KTILE * DDIM; idx += 256) {
            int i  = idx & 63;
            int kk = idx >> 6;
            wt[i][kk] = w[(size_t)(kt + kk) * DDIM + i];
        }
        __syncthreads();

        for (int kk = 0; kk < KTILE; kk += 16) {
            unsigned long long a[8];
            #pragma unroll
            for (int j = 0; j < 8; ++j) a[j] = 0ull;

            // 8 packed chains (16 codebook entries). Each chain component still
            // accumulates i = 0..63 sequentially -> reference-identical rounding.
            #pragma unroll
            for (int i = 0; i < DDIM; ++i) {
                unsigned long long f2;
                asm("mov.b64 %0, {%1, %1};" : "=l"(f2) : "f"(f[i]));
                const ulonglong2* wp = (const ulonglong2*)&wt[i][kk];
                ulonglong2 w01 = wp[0];   // k+0..3
                ulonglong2 w23 = wp[1];   // k+4..7
                ulonglong2 w45 = wp[2];   // k+8..11
                ulonglong2 w67 = wp[3];   // k+12..15
                ffma2(a[0], f2, w01.x);
                ffma2(a[1], f2, w01.y);
                ffma2(a[2], f2, w23.x);
                ffma2(a[3], f2, w23.y);
                ffma2(a[4], f2, w45.x);
                ffma2(a[5], f2, w45.y);
                ffma2(a[6], f2, w67.x);
                ffma2(a[7], f2, w67.y);
            }
            #pragma unroll
            for (int j = 0; j < 8; ++j) {
                float lo, hi;
                asm("mov.b64 {%0, %1}, %2;" : "=f"(lo), "=f"(hi) : "l"(a[j]));
                int k0 = kt + kk + 2 * j;
                // ref: t1 = fl(S + w2[k]); d = fl(t1 - fl(2*fw)); 2*fw exact -> fused ok
                float t1 = __fadd_rn(S, w2s[k0]);
                float d  = fmaf(-2.0f, lo, t1);
                if (d < dmin) { dmin = d; kbest = k0; }   // strict <: first index wins
                float t2 = __fadd_rn(S, w2s[k0 + 1]);
                float d2 = fmaf(-2.0f, hi, t2);
                if (d2 < dmin) { dmin = d2; kbest = k0 + 1; }
            }
        }
    }

    g_idx[row] = kbest;
    atomicAdd(&hist[kbest], 1);

    // Quantized output (straight-through forward: fl(x + fl(q - x))) + loss partials
    const float* wr = w + (size_t)kbest * DDIM;
    float* qo = out + (size_t)b * 262144 + hw;
    float lsum = 0.0f;
    #pragma unroll
    for (int c = 0; c < DDIM; ++c) {
        float q  = wr[c];
        float dd = __fsub_rn(q, f[c]);
        qo[c * 4096] = __fadd_rn(f[c], dd);
        lsum = fmaf(dd, dd, lsum);
    }
    #pragma unroll
    for (int o = 16; o; o >>= 1) lsum += __shfl_down_sync(0xffffffffu, lsum, o);
    if ((tid & 31) == 0) atomicAdd(&g_loss, (double)lsum);

    __syncthreads();
    for (int i = tid; i < KCODES; i += 256)
        if (hist[i]) atomicAdd(&g_counts[i], hist[i]);
}

// Zero-fill encodings with vectorized stores. Base (out+ENC_OFF) is only 4B
// aligned; (enc+3) is 16B aligned, so vector-fill [3, ENCSIZE-1) and patch edges.
__global__ void zfill_kernel(float* __restrict__ enc) {
    float4* p = (float4*)(enc + 3);
    const unsigned NV = (ENCSIZE - 4) / 4;   // 16777215 float4s
    unsigned stride = gridDim.x * blockDim.x;
    float4 z = make_float4(0.f, 0.f, 0.f, 0.f);
    for (unsigned i = blockIdx.x * blockDim.x + threadIdx.x; i < NV; i += stride)
        p[i] = z;
    if (blockIdx.x == 0 && threadIdx.x == 0) {
        enc[0] = 0.f; enc[1] = 0.f; enc[2] = 0.f; enc[ENCSIZE - 1] = 0.f;
    }
}

// Scatter the ones: 131072 scalar stores.
__global__ void ones_kernel(float* __restrict__ enc) {
    int n = blockIdx.x * 256 + threadIdx.x;
    enc[(size_t)n * KCODES + g_idx[n]] = 1.0f;
}

__global__ void final_kernel(float* __restrict__ out) {
    __shared__ double red[KCODES];
    int t = threadIdx.x;
    float p = (float)g_counts[t] * (1.0f / 131072.0f);   // exact (power-of-2 divide)
    float term = __fmul_rn(p, logf(__fadd_rn(p, 1e-10f)));
    red[t] = (double)term;
    __syncthreads();
    for (int s = 256; s; s >>= 1) {
        if (t < s) red[t] += red[t + s];
        __syncthreads();
    }
    if (t == 0) {
        out[PERP_OFF] = expf(-(float)red[0]);
        float m = (float)(g_loss / (double)QSIZE);
        out[QSIZE] = __fadd_rn(m, __fmul_rn(0.25f, m));
    }
}

extern "C" void kernel_launch(void* const* d_in, const int* in_sizes, int n_in,
                              void* d_out, int out_size) {
    const float* x = (const float*)d_in[0];
    const float* w = (const float*)d_in[1];
    float* out = (float*)d_out;

    init_kernel<<<1, 512>>>();
    w2_kernel<<<1, 512>>>(w);
    main_kernel<<<NROWS / 256, 256>>>(x, w, out);
    zfill_kernel<<<2368, 256>>>(out + ENC_OFF);
    ones_kernel<<<NROWS / 256, 256>>>(out + ENC_OFF);
    final_kernel<<<1, KCODES>>>(out);
}

// round 3
// speedup vs baseline: 1.6316x; 1.2594x over previous
#include <cuda_runtime.h>
#include <math.h>

#define NROWS   131072
#define DDIM    64
#define KCODES  512
#define KT      128              // codebook tile
#define QSIZE   8388608
#define ENCSIZE 67108864
#define ENC_OFF (QSIZE + 1)
#define PERP_OFF (QSIZE + 1 + ENCSIZE)

__device__ int    g_idx[NROWS];
__device__ int    g_counts[KCODES];
__device__ double g_loss;
__device__ float  g_w2[KCODES];

__global__ void init_kernel() {
    int t = threadIdx.x;
    if (t < KCODES) g_counts[t] = 0;
    if (t == 0) g_loss = 0.0;
}

// w2[k] = sum_i round(w[k][i]^2), sequential non-fused (mimic jnp.sum(w*w,axis=1)).
__global__ void w2_kernel(const float* __restrict__ w) {
    int k = blockIdx.x * blockDim.x + threadIdx.x;
    if (k < KCODES) {
        float s = 0.0f;
        #pragma unroll 8
        for (int i = 0; i < DDIM; ++i) {
            float v = w[k * DDIM + i];
            s = __fadd_rn(s, __fmul_rn(v, v));
        }
        g_w2[k] = s;
    }
}

// Packed dual fp32 FMA, each lane rounds identically to scalar fma.rn.
__device__ __forceinline__ void ffma2(unsigned long long& acc,
                                      unsigned long long a,
                                      unsigned long long b) {
    asm("fma.rn.f32x2 %0, %1, %2, %0;" : "+l"(acc) : "l"(a), "l"(b));
}
__device__ __forceinline__ unsigned long long dup2(float v) {
    unsigned long long r;
    asm("mov.b64 %0, {%1, %1};" : "=l"(r) : "f"(v));
    return r;
}

// Main kernel: 2 rows per thread (halves LDS traffic per FMA).
// Reference-identical rounding per distance; first-index argmin tie-break.
__global__ __launch_bounds__(128, 2)
void main_kernel(const float* __restrict__ x, const float* __restrict__ w,
                 float* __restrict__ out) {
    __shared__ __align__(16) float wt[DDIM][KT + 4];   // transposed tile, 528B row stride
    __shared__ float w2s[KCODES];
    __shared__ int   hist[KCODES];

    int tid = threadIdx.x;
    for (int i = tid; i < KCODES; i += 128) { hist[i] = 0; w2s[i] = g_w2[i]; }

    int row0 = blockIdx.x * 256 + tid;         // grid = 512 blocks, 256 rows/block
    int row1 = row0 + 128;
    int b0 = row0 >> 12, hw0 = row0 & 4095;
    int b1 = row1 >> 12, hw1 = row1 & 4095;
    const float* xp0 = x + (size_t)b0 * 262144 + hw0;
    const float* xp1 = x + (size_t)b1 * 262144 + hw1;

    float f0[DDIM], f1[DDIM];
    #pragma unroll
    for (int c = 0; c < DDIM; ++c) { f0[c] = xp0[c * 4096]; f1[c] = xp1[c * 4096]; }

    // S = sum(f*f): sequential, NON-fused (jnp squares then reduces).
    float S0 = 0.0f, S1 = 0.0f;
    #pragma unroll
    for (int c = 0; c < DDIM; ++c) {
        S0 = __fadd_rn(S0, __fmul_rn(f0[c], f0[c]));
        S1 = __fadd_rn(S1, __fmul_rn(f1[c], f1[c]));
    }

    float dmin0 = __int_as_float(0x7f800000), dmin1 = dmin0;
    int kb0 = 0, kb1 = 0;

    for (int kt = 0; kt < KCODES; kt += KT) {
        __syncthreads();
        for (int idx = tid; idx < KT * DDIM; idx += 128) {
            int i  = idx & 63;
            int kk = idx >> 6;
            wt[i][kk] = w[(size_t)(kt + kk) * DDIM + i];
        }
        __syncthreads();

        for (int kk = 0; kk < KT; kk += 16) {
            unsigned long long a0[8], a1[8];
            #pragma unroll
            for (int j = 0; j < 8; ++j) { a0[j] = 0ull; a1[j] = 0ull; }

            // 16 independent packed chains; each chain's i-order stays 0..63
            // sequential -> bit-identical to the reference dot product.
            #pragma unroll
            for (int i = 0; i < DDIM; ++i) {
                unsigned long long fa = dup2(f0[i]);
                unsigned long long fb = dup2(f1[i]);
                const ulonglong2* wp = (const ulonglong2*)&wt[i][kk];
                ulonglong2 wA = wp[0], wB = wp[1], wC = wp[2], wD = wp[3];
                ffma2(a0[0], fa, wA.x);  ffma2(a1[0], fb, wA.x);
                ffma2(a0[1], fa, wA.y);  ffma2(a1[1], fb, wA.y);
                ffma2(a0[2], fa, wB.x);  ffma2(a1[2], fb, wB.x);
                ffma2(a0[3], fa, wB.y);  ffma2(a1[3], fb, wB.y);
                ffma2(a0[4], fa, wC.x);  ffma2(a1[4], fb, wC.x);
                ffma2(a0[5], fa, wC.y);  ffma2(a1[5], fb, wC.y);
                ffma2(a0[6], fa, wD.x);  ffma2(a1[6], fb, wD.x);
                ffma2(a0[7], fa, wD.y);  ffma2(a1[7], fb, wD.y);
            }
            #pragma unroll
            for (int j = 0; j < 8; ++j) {
                int k0 = kt + kk + 2 * j;
                float lo0, hi0, lo1, hi1;
                asm("mov.b64 {%0, %1}, %2;" : "=f"(lo0), "=f"(hi0) : "l"(a0[j]));
                asm("mov.b64 {%0, %1}, %2;" : "=f"(lo1), "=f"(hi1) : "l"(a1[j]));
                // ref: t = fl(S + w2[k]); d = fl(t - fl(2*fw)); 2*fw exact -> fused ok
                float ta = __fadd_rn(S0, w2s[k0]);
                float da = fmaf(-2.0f, lo0, ta);
                if (da < dmin0) { dmin0 = da; kb0 = k0; }
                float tb = __fadd_rn(S0, w2s[k0 + 1]);
                float db = fmaf(-2.0f, hi0, tb);
                if (db < dmin0) { dmin0 = db; kb0 = k0 + 1; }
                float tc = __fadd_rn(S1, w2s[k0]);
                float dc = fmaf(-2.0f, lo1, tc);
                if (dc < dmin1) { dmin1 = dc; kb1 = k0; }
                float td = __fadd_rn(S1, w2s[k0 + 1]);
                float dd = fmaf(-2.0f, hi1, td);
                if (dd < dmin1) { dmin1 = dd; kb1 = k0 + 1; }
            }
        }
    }

    g_idx[row0] = kb0;
    g_idx[row1] = kb1;
    atomicAdd(&hist[kb0], 1);
    atomicAdd(&hist[kb1], 1);

    // Quantized output (straight-through forward: fl(x + fl(q - x))) + loss partials
    const float* wr0 = w + (size_t)kb0 * DDIM;
    const float* wr1 = w + (size_t)kb1 * DDIM;
    float* qo0 = out + (size_t)b0 * 262144 + hw0;
    float* qo1 = out + (size_t)b1 * 262144 + hw1;
    float lsum = 0.0f;
    #pragma unroll
    for (int c = 0; c < DDIM; ++c) {
        float q0 = wr0[c];
        float d0 = __fsub_rn(q0, f0[c]);
        qo0[c * 4096] = __fadd_rn(f0[c], d0);
        lsum = fmaf(d0, d0, lsum);
        float q1 = wr1[c];
        float d1 = __fsub_rn(q1, f1[c]);
        qo1[c * 4096] = __fadd_rn(f1[c], d1);
        lsum = fmaf(d1, d1, lsum);
    }
    #pragma unroll
    for (int o = 16; o; o >>= 1) lsum += __shfl_down_sync(0xffffffffu, lsum, o);
    if ((tid & 31) == 0) atomicAdd(&g_loss, (double)lsum);

    __syncthreads();
    for (int i = tid; i < KCODES; i += 128)
        if (hist[i]) atomicAdd(&g_counts[i], hist[i]);
}

// Fused encodings: zero-fill + one-hot in a single float4 store stream.
// Base (enc+3) is 16B aligned; k0 = (3+4i)&511 is ≡3 (mod 4), so a float4
// straddles a row boundary only when k0 == 511.
__global__ void enc_kernel(float* __restrict__ enc) {
    float4* p = (float4*)(enc + 3);
    const unsigned NV = (ENCSIZE - 4) / 4;
    unsigned stride = gridDim.x * blockDim.x;
    for (unsigned i = blockIdx.x * blockDim.x + threadIdx.x; i < NV; i += stride) {
        unsigned e0 = 3u + 4u * i;
        unsigned n0 = e0 >> 9;
        unsigned k0 = e0 & 511u;
        float4 v = make_float4(0.f, 0.f, 0.f, 0.f);
        if (k0 != 511u) {
            unsigned d = (unsigned)g_idx[n0] - k0;
            if (d < 4u) ((float*)&v)[d] = 1.0f;
        } else {
            if (g_idx[n0] == 511) v.x = 1.0f;
            int j = g_idx[n0 + 1];
            if (j < 3) ((float*)&v)[j + 1] = 1.0f;
        }
        p[i] = v;
    }
    if (blockIdx.x == 0 && threadIdx.x == 0) {
        int j0 = g_idx[0];
        enc[0] = (j0 == 0) ? 1.0f : 0.0f;
        enc[1] = (j0 == 1) ? 1.0f : 0.0f;
        enc[2] = (j0 == 2) ? 1.0f : 0.0f;
        enc[ENCSIZE - 1] = (g_idx[NROWS - 1] == 511) ? 1.0f : 0.0f;
    }
}

__global__ void final_kernel(float* __restrict__ out) {
    __shared__ double red[KCODES];
    int t = threadIdx.x;
    float p = (float)g_counts[t] * (1.0f / 131072.0f);
    float term = __fmul_rn(p, logf(__fadd_rn(p, 1e-10f)));
    red[t] = (double)term;
    __syncthreads();
    for (int s = 256; s; s >>= 1) {
        if (t < s) red[t] += red[t + s];
        __syncthreads();
    }
    if (t == 0) {
        out[PERP_OFF] = expf(-(float)red[0]);
        float m = (float)(g_loss / (double)QSIZE);
        out[QSIZE] = __fadd_rn(m, __fmul_rn(0.25f, m));
    }
}

extern "C" void kernel_launch(void* const* d_in, const int* in_sizes, int n_in,
                              void* d_out, int out_size) {
    const float* x = (const float*)d_in[0];
    const float* w = (const float*)d_in[1];
    float* out = (float*)d_out;

    init_kernel<<<1, 512>>>();
    w2_kernel<<<1, 512>>>(w);
    main_kernel<<<512, 128>>>(x, w, out);
    enc_kernel<<<2368, 256>>>(out + ENC_OFF);
    final_kernel<<<1, KCODES>>>(out);
}